// round 9
// baseline (speedup 1.0000x reference)
#include <cuda_runtime.h>

// ---------------------------------------------------------------------------
// PC_RNN_HC_A round 8: persistent kernel + grid barrier + cp.async double
// buffering + A-operand broadcast LDG + packed fma.rn.f32x2 (FFMA2) math.
// ---------------------------------------------------------------------------

#define GRID      128
#define NTHREADS  256

#define SEQ   512
#define BATCH 256
#define OUTD  256
#define CAUS  64
#define HID   512

#define SB 68   // smem row stride (floats): 68 mod 32 = 4 -> conflict-free
                // LDS.128 within 8-lane phases; rows remain 16B aligned.

typedef unsigned long long u64;

// Persistent state (device globals: allocation is forbidden)
__device__ float g_h  [BATCH * HID];
__device__ float g_th [BATCH * HID];
__device__ float g_hp [BATCH * HID];
__device__ float g_tp [BATCH * HID];
__device__ float g_eh [BATCH * HID];
__device__ float g_err[BATCH * OUTD];
__device__ float g_c  [BATCH * CAUS];
__device__ float g_woT[HID * OUTD];   // woT[i][o] = w_o[o][i]
__device__ float g_wcT[CAUS * HID];   // wcT[c][i] = w_c[i][c]

__device__ unsigned g_bar_count;      // zero at module load
__device__ unsigned g_bar_gen;

// ---------------------------------------------------------------------------
// Grid-wide barrier (monotone generation; replay-safe; grid <= #SMs).
// ---------------------------------------------------------------------------
__device__ __forceinline__ void grid_sync() {
    __syncthreads();
    if (threadIdx.x == 0) {
        volatile unsigned* genp = &g_bar_gen;
        unsigned my = *genp;
        __threadfence();
        unsigned prev = atomicAdd(&g_bar_count, 1u);
        if (prev == GRID - 1u) {
            g_bar_count = 0u;
            __threadfence();
            atomicExch(&g_bar_gen, my + 1u);
        } else {
            while (*genp == my) { }
            __threadfence();
        }
    }
    __syncthreads();
}

// ---------------------------------------------------------------------------
// Packed f32x2 FMA: acc(lo,hi) += a(lo,hi)*b(lo,hi)   [PTX-only FFMA2]
// ---------------------------------------------------------------------------
__device__ __forceinline__ void ffma2(u64 &acc, u64 a, u64 b) {
    asm("fma.rn.f32x2 %0, %1, %2, %0;" : "+l"(acc) : "l"(a), "l"(b));
}
__device__ __forceinline__ float fsum2(u64 v) {
    float lo, hi;
    asm("mov.b64 {%0,%1}, %2;" : "=f"(lo), "=f"(hi) : "l"(v));
    return lo + hi;
}

// ---------------------------------------------------------------------------
// cp.async helpers
// ---------------------------------------------------------------------------
__device__ __forceinline__ void cp_async16(float* s, const float* g) {
    unsigned sa = (unsigned)__cvta_generic_to_shared(s);
    asm volatile("cp.async.ca.shared.global [%0], [%1], 16;" :: "r"(sa), "l"(g));
}
__device__ __forceinline__ void cp_commit() { asm volatile("cp.async.commit_group;"); }
__device__ __forceinline__ void cp_wait0()  { asm volatile("cp.async.wait_group 0;"); }

// Fill one B tile: TN rows x 64 k, k-major source (leading dim ldb), stride SB.
template<int TN>
__device__ __forceinline__ void fill_b(float* bs, const float* __restrict__ B,
                                       int ldb, int k0) {
    const int tid = threadIdx.x;
#pragma unroll
    for (int it = 0; it < (TN * 16) / NTHREADS; it++) {
        int idx = tid + it * NTHREADS;
        int n   = idx >> 4;
        int k4  = idx & 15;
        cp_async16(bs + n * SB + k4 * 4, B + n * ldb + k0 + k4 * 4);
    }
}

// ---------------------------------------------------------------------------
// NT GEMM, packed accumulators:
//   accP[im][in] (f32x2) accumulates A[ty+16im][k] * B[tx+16in][k]
// A direct from global (full warp broadcast per row), B via cp.async smem.
// ---------------------------------------------------------------------------
template<int RM, int RN>
__device__ __forceinline__ void gemm_nt(float* bbuf,
                                        const float* __restrict__ A, int lda,
                                        const float* __restrict__ B, int ldb,
                                        int ktiles,
                                        u64 (&accP)[RM][RN]) {
    constexpr int TN = 16 * RN;
    const int tx = threadIdx.x & 15;
    const int ty = threadIdx.x >> 4;

    __syncthreads();                       // bbuf may still be read by prev phase
    fill_b<TN>(bbuf, B, ldb, 0);
    cp_commit();

    const float* Ar[RM];
#pragma unroll
    for (int im = 0; im < RM; im++) Ar[im] = A + (ty + 16 * im) * lda;

    int buf = 0;
    for (int kt = 0; kt < ktiles; kt++) {
        cp_wait0();
        __syncthreads();
        if (kt + 1 < ktiles) {
            fill_b<TN>(bbuf + (buf ^ 1) * TN * SB, B, ldb, (kt + 1) * 64);
            cp_commit();
        }
        const float* bs = bbuf + buf * TN * SB;
        const int kb = kt * 64;
#pragma unroll
        for (int k4 = 0; k4 < 16; k4++) {
            ulonglong2 a2[RM], b2[RN];
#pragma unroll
            for (int im = 0; im < RM; im++)
                a2[im] = *reinterpret_cast<const ulonglong2*>(Ar[im] + kb + k4 * 4);
#pragma unroll
            for (int in = 0; in < RN; in++)
                b2[in] = *reinterpret_cast<const ulonglong2*>(bs + (tx + 16 * in) * SB + k4 * 4);
#pragma unroll
            for (int im = 0; im < RM; im++)
#pragma unroll
                for (int in = 0; in < RN; in++) {
                    ffma2(accP[im][in], a2[im].x, b2[in].x);
                    ffma2(accP[im][in], a2[im].y, b2[in].y);
                }
        }
        buf ^= 1;
    }
}

// ---------------------------------------------------------------------------
// Phase D: 128 compute threads, each a 512-length dot product (packed).
// All 256 threads participate in fills/syncs.
// ---------------------------------------------------------------------------
__device__ __forceinline__ float gemm_d(float* bbuf,
                                        const float* __restrict__ Arow,
                                        const float* __restrict__ B) {
    const int tid = threadIdx.x;
    __syncthreads();
    fill_b<16>(bbuf, B, HID, 0);
    cp_commit();
    u64 accP = 0ull;
    int buf = 0;
    for (int kt = 0; kt < 8; kt++) {
        cp_wait0();
        __syncthreads();
        if (kt < 7) {
            fill_b<16>(bbuf + (buf ^ 1) * 16 * SB, B, HID, (kt + 1) * 64);
            cp_commit();
        }
        if (tid < 128) {
            const float* bs = bbuf + buf * 16 * SB;
            const int tx = tid & 15;
            const int kb = kt * 64;
#pragma unroll
            for (int k4 = 0; k4 < 16; k4++) {
                ulonglong2 a = *reinterpret_cast<const ulonglong2*>(Arow + kb + k4 * 4);
                ulonglong2 b = *reinterpret_cast<const ulonglong2*>(bs + tx * SB + k4 * 4);
                ffma2(accP, a.x, b.x);
                ffma2(accP, a.y, b.y);
            }
        }
        buf ^= 1;
    }
    return fsum2(accP);
}

// ---------------------------------------------------------------------------
// Main persistent kernel
// ---------------------------------------------------------------------------
__global__ void __launch_bounds__(NTHREADS, 1)
pc_rnn_kernel(const float* __restrict__ x,
              const float* __restrict__ c_init,
              const float* __restrict__ h_init,
              const float* __restrict__ w_o,
              const float* __restrict__ b_o,
              const float* __restrict__ w_c,
              const float* __restrict__ w_r,
              const float* __restrict__ b_r,
              float* __restrict__ out) {
    __shared__ float bbuf[2 * 32 * SB];   // 17408 B double buffer (max TN=32)

    const int bid = blockIdx.x;
    const int tid = threadIdx.x;
    const int tx  = tid & 15, ty = tid >> 4;
    const int gtid = bid * NTHREADS + tid;
    const int gstride = GRID * NTHREADS;

    // ---- init state + weight transposes (fresh every launch/replay) ----
    for (int i = gtid; i < BATCH * HID; i += gstride) {
        float h = h_init[i];
        g_h[i]  = h;
        g_th[i] = tanhf(h);
    }
    for (int i = gtid; i < BATCH * CAUS; i += gstride)
        g_c[i] = c_init[i];
    for (int i = gtid; i < HID * OUTD; i += gstride) {   // woT[i][o] = w_o[o][i]
        int hh = i >> 8, o = i & (OUTD - 1);
        g_woT[i] = w_o[o * HID + hh];
    }
    for (int i = gtid; i < CAUS * HID; i += gstride) {   // wcT[c][i] = w_c[i][c]
        int c = i >> 9, hh = i & (HID - 1);
        g_wcT[i] = w_c[hh * CAUS + c];
    }
    grid_sync();

    for (int t = 0; t < SEQ; t++) {
        // ---- Phase A: h_prior = 0.9*h + 0.1*(th@Wr^T + c@Wc^T + b_r); tp=tanh ----
        // 256x512 out, 32x32 tiles, 8x16 grid = 128 CTAs
        {
            const int row0 = (bid >> 4) * 32, col0 = (bid & 15) * 32;
            u64 accP[2][2] = {};
            gemm_nt<2, 2>(bbuf, g_th + row0 * HID, HID,
                          w_r + col0 * HID, HID, HID / 64, accP);
            gemm_nt<2, 2>(bbuf, g_c + row0 * CAUS, CAUS,
                          w_c + col0 * CAUS, CAUS, 1, accP);
#pragma unroll
            for (int im = 0; im < 2; im++)
#pragma unroll
                for (int in = 0; in < 2; in++) {
                    int r   = row0 + ty + 16 * im;
                    int ci  = col0 + tx + 16 * in;
                    int idx = r * HID + ci;
                    float hp = 0.9f * g_h[idx] + 0.1f * (fsum2(accP[im][in]) + b_r[ci]);
                    g_hp[idx] = hp;
                    g_tp[idx] = tanhf(hp);
                }
        }
        grid_sync();

        // ---- Phase B: err = tp@Wo^T + b_o - x_t  (streamed to out too) ----
        // 256x256 out, 32x16 tiles, 8x16 grid = 128 CTAs (RN=1 cuts smem/MAC)
        {
            const int row0 = (bid >> 4) * 32, col0 = (bid & 15) * 16;
            u64 accP[2][1] = {};
            gemm_nt<2, 1>(bbuf, g_tp + row0 * HID, HID,
                          w_o + col0 * HID, HID, HID / 64, accP);
#pragma unroll
            for (int im = 0; im < 2; im++) {
                int r  = row0 + ty + 16 * im;
                int o  = col0 + tx;
                int xi = (t * BATCH + r) * OUTD + o;
                float e = fsum2(accP[im][0]) + b_o[o] - x[xi];
                g_err[r * OUTD + o] = e;
                out[xi] = e;
            }
        }
        grid_sync();

        // ---- Phase C: g = err@Wo (via woT); eh = 0.1*(1-tp^2)*g; h_post ----
        // 256x512 out, 32x32 tiles, 8x16 grid = 128 CTAs
        {
            const int row0 = (bid >> 4) * 32, col0 = (bid & 15) * 32;
            u64 accP[2][2] = {};
            gemm_nt<2, 2>(bbuf, g_err + row0 * OUTD, OUTD,
                          g_woT + col0 * OUTD, OUTD, OUTD / 64, accP);
#pragma unroll
            for (int im = 0; im < 2; im++)
#pragma unroll
                for (int in = 0; in < 2; in++) {
                    int r   = row0 + ty + 16 * im;
                    int ci  = col0 + tx + 16 * in;
                    int idx = r * HID + ci;
                    float tp = g_tp[idx];
                    float eh = 0.1f * (1.0f - tp * tp) * fsum2(accP[im][in]);
                    float hpost = g_hp[idx] - eh;
                    g_eh[idx] = eh;
                    g_h[idx]  = hpost;
                    g_th[idx] = tanhf(hpost);
                }
        }
        grid_sync();

        // ---- Phase D: c -= 0.1 * (eh @ Wc)  (via wcT) ----
        // 256x64 out, 8x16 tiles, 32x4 grid = 128 CTAs; 128 compute threads
        {
            const int row0 = (bid >> 2) * 8, col0 = (bid & 3) * 16;
            const int r = row0 + (ty & 7);               // valid for tid<128
            float a = gemm_d(bbuf, g_eh + r * HID, g_wcT + col0 * HID);
            if (tid < 128)
                g_c[r * CAUS + col0 + tx] -= 0.1f * a;
        }
        grid_sync();
    }
}

// ---------------------------------------------------------------------------
// Launch: single graph-capturable kernel node, no allocation.
// Inputs (metadata order): x, c_init, h_init, w_o, b_o, w_c, w_r, b_r
// ---------------------------------------------------------------------------
extern "C" void kernel_launch(void* const* d_in, const int* in_sizes, int n_in,
                              void* d_out, int out_size) {
    const float* x      = (const float*)d_in[0];
    const float* c_init = (const float*)d_in[1];
    const float* h_init = (const float*)d_in[2];
    const float* w_o    = (const float*)d_in[3];
    const float* b_o    = (const float*)d_in[4];
    const float* w_c    = (const float*)d_in[5];
    const float* w_r    = (const float*)d_in[6];
    const float* b_r    = (const float*)d_in[7];
    float* out = (float*)d_out;

    pc_rnn_kernel<<<GRID, NTHREADS>>>(x, c_init, h_init, w_o, b_o, w_c, w_r, b_r, out);
}